// round 1
// baseline (speedup 1.0000x reference)
#include <cuda_runtime.h>

#define B_   2
#define S_   2048
#define E_   1024
#define H_   16
#define DH_  64
#define FF_  4096
#define TOK  (B_*S_)   // 4096

// ---------------- scratch (no allocs allowed) ----------------
__device__ float g_nx  [TOK*(size_t)E_];
__device__ float g_q   [(size_t)B_*H_*S_*DH_];
__device__ float g_k   [(size_t)B_*H_*S_*DH_];
__device__ float g_v   [(size_t)B_*H_*S_*DH_];
__device__ float g_attn[TOK*(size_t)E_];
__device__ float g_x1  [TOK*(size_t)E_];
__device__ float g_nx2 [TOK*(size_t)E_];
__device__ float g_ffn [TOK*(size_t)FF_];

__device__ __forceinline__ float neg_inf() { return __int_as_float(0xff800000u); }

// ---------------- LayerNorm: one block per token ----------------
__global__ void __launch_bounds__(256) ln_kernel(
    const float* __restrict__ x, const float* __restrict__ g,
    const float* __restrict__ bta, float* __restrict__ out)
{
    __shared__ float sh1[8], sh2[8];
    int tok = blockIdx.x;
    int t = threadIdx.x;
    const float4* xr = (const float4*)(x + (size_t)tok * E_);
    float4 v = xr[t];
    float sum = v.x + v.y + v.z + v.w;
    float sq  = v.x*v.x + v.y*v.y + v.z*v.z + v.w*v.w;
    #pragma unroll
    for (int o = 16; o > 0; o >>= 1) {
        sum += __shfl_xor_sync(0xffffffffu, sum, o);
        sq  += __shfl_xor_sync(0xffffffffu, sq,  o);
    }
    if ((t & 31) == 0) { sh1[t >> 5] = sum; sh2[t >> 5] = sq; }
    __syncthreads();
    if (t < 32) {
        sum = (t < 8) ? sh1[t] : 0.f;
        sq  = (t < 8) ? sh2[t] : 0.f;
        #pragma unroll
        for (int o = 4; o > 0; o >>= 1) {
            sum += __shfl_xor_sync(0xffffffffu, sum, o);
            sq  += __shfl_xor_sync(0xffffffffu, sq,  o);
        }
        if (t == 0) { sh1[0] = sum; sh2[0] = sq; }
    }
    __syncthreads();
    sum = sh1[0]; sq = sh2[0];
    float mu  = sum * (1.0f / E_);
    float var = sq * (1.0f / E_) - mu * mu;
    float rs  = rsqrtf(var + 1e-5f);
    float4 gv = ((const float4*)g)[t];
    float4 bv = ((const float4*)bta)[t];
    float4 o4;
    o4.x = (v.x - mu) * rs * gv.x + bv.x;
    o4.y = (v.y - mu) * rs * gv.y + bv.y;
    o4.z = (v.z - mu) * rs * gv.z + bv.z;
    o4.w = (v.w - mu) * rs * gv.w + bv.w;
    ((float4*)(out + (size_t)tok * E_))[t] = o4;
}

// ---------------- QKV projection GEMM ----------------
// A: nx [4096 x 1024], W: [H,E,DH] block layout, out: [B,H,S,DH]
__global__ void __launch_bounds__(256) gemm_qkv_kernel(
    const float* __restrict__ A, const float* __restrict__ W,
    float* __restrict__ out)
{
    __shared__ float As[8][132];
    __shared__ float Bs[8][128];
    const int K = E_;
    int bm = blockIdx.y, bn = blockIdx.x;
    int t = threadIdx.x;
    int tx = t & 15, ty = t >> 4;
    float acc[8][8];
    #pragma unroll
    for (int i = 0; i < 8; i++)
        #pragma unroll
        for (int j = 0; j < 8; j++) acc[i][j] = 0.f;

    int a_row = t >> 1, a_k4 = (t & 1) << 2;
    int b_k = t >> 5,  b_j4 = (t & 31) << 2;
    int nb = bn * 128 + b_j4;
    const float* wbase = W + (size_t)(nb >> 6) * (E_ * DH_) + (size_t)b_k * DH_ + (nb & 63);
    const float* abase = A + (size_t)(bm * 128 + a_row) * K + a_k4;

    for (int kk = 0; kk < K; kk += 8) {
        float4 av = *(const float4*)(abase + kk);
        As[a_k4 + 0][a_row] = av.x;
        As[a_k4 + 1][a_row] = av.y;
        As[a_k4 + 2][a_row] = av.z;
        As[a_k4 + 3][a_row] = av.w;
        float4 bv = *(const float4*)(wbase + (size_t)kk * DH_);
        *(float4*)(&Bs[b_k][b_j4]) = bv;
        __syncthreads();
        #pragma unroll
        for (int k = 0; k < 8; k++) {
            float ar[8], br[8];
            #pragma unroll
            for (int i = 0; i < 8; i++) ar[i] = As[k][ty * 8 + i];
            #pragma unroll
            for (int j = 0; j < 8; j++) br[j] = Bs[k][tx * 8 + j];
            #pragma unroll
            for (int i = 0; i < 8; i++)
                #pragma unroll
                for (int j = 0; j < 8; j++)
                    acc[i][j] = fmaf(ar[i], br[j], acc[i][j]);
        }
        __syncthreads();
    }
    #pragma unroll
    for (int i = 0; i < 8; i++) {
        int m = bm * 128 + ty * 8 + i;
        int bb = m >> 11, s = m & (S_ - 1);
        #pragma unroll
        for (int j = 0; j < 8; j += 4) {
            int n = bn * 128 + tx * 8 + j;
            int h = n >> 6, d = n & 63;
            float4 o4 = make_float4(acc[i][j], acc[i][j+1], acc[i][j+2], acc[i][j+3]);
            *(float4*)(out + (((size_t)(bb * H_ + h)) * S_ + s) * DH_ + d) = o4;
        }
    }
}

// ---------------- generic GEMM with epilogue ----------------
// C[M,N] = op(A[M,K] @ W[K,N] + bias[N] (+ res[M,N]))
template<bool RELU, bool RES>
__global__ void __launch_bounds__(256) gemm_ep_kernel(
    const float* __restrict__ A, const float* __restrict__ W,
    const float* __restrict__ bias, const float* __restrict__ res,
    float* __restrict__ out, int M, int N, int K)
{
    __shared__ float As[8][132];
    __shared__ float Bs[8][128];
    int bm = blockIdx.y, bn = blockIdx.x;
    int t = threadIdx.x;
    int tx = t & 15, ty = t >> 4;
    float acc[8][8];
    #pragma unroll
    for (int i = 0; i < 8; i++)
        #pragma unroll
        for (int j = 0; j < 8; j++) acc[i][j] = 0.f;

    int a_row = t >> 1, a_k4 = (t & 1) << 2;
    int b_k = t >> 5,  b_j4 = (t & 31) << 2;
    const float* abase = A + (size_t)(bm * 128 + a_row) * K + a_k4;
    const float* wbase = W + (size_t)b_k * N + bn * 128 + b_j4;

    for (int kk = 0; kk < K; kk += 8) {
        float4 av = *(const float4*)(abase + kk);
        As[a_k4 + 0][a_row] = av.x;
        As[a_k4 + 1][a_row] = av.y;
        As[a_k4 + 2][a_row] = av.z;
        As[a_k4 + 3][a_row] = av.w;
        float4 bv = *(const float4*)(wbase + (size_t)kk * N);
        *(float4*)(&Bs[b_k][b_j4]) = bv;
        __syncthreads();
        #pragma unroll
        for (int k = 0; k < 8; k++) {
            float ar[8], br[8];
            #pragma unroll
            for (int i = 0; i < 8; i++) ar[i] = As[k][ty * 8 + i];
            #pragma unroll
            for (int j = 0; j < 8; j++) br[j] = Bs[k][tx * 8 + j];
            #pragma unroll
            for (int i = 0; i < 8; i++)
                #pragma unroll
                for (int j = 0; j < 8; j++)
                    acc[i][j] = fmaf(ar[i], br[j], acc[i][j]);
        }
        __syncthreads();
    }
    #pragma unroll
    for (int i = 0; i < 8; i++) {
        int m = bm * 128 + ty * 8 + i;
        size_t rowoff = (size_t)m * N;
        #pragma unroll
        for (int j = 0; j < 8; j += 4) {
            int n = bn * 128 + tx * 8 + j;
            float4 o4 = make_float4(acc[i][j], acc[i][j+1], acc[i][j+2], acc[i][j+3]);
            float4 bv = *(const float4*)(bias + n);
            o4.x += bv.x; o4.y += bv.y; o4.z += bv.z; o4.w += bv.w;
            if (RES) {
                float4 rv = *(const float4*)(res + rowoff + n);
                o4.x += rv.x; o4.y += rv.y; o4.z += rv.z; o4.w += rv.w;
            }
            if (RELU) {
                o4.x = fmaxf(o4.x, 0.f); o4.y = fmaxf(o4.y, 0.f);
                o4.z = fmaxf(o4.z, 0.f); o4.w = fmaxf(o4.w, 0.f);
            }
            *(float4*)(out + rowoff + n) = o4;
        }
    }
}

// ---------------- flash attention (causal), 64x64 tiles ----------------
// Q,K,V: [B,H,S,DH]; O written in concat layout [B,S,E]
__global__ void __launch_bounds__(256) flash_kernel(
    const float* __restrict__ Q, const float* __restrict__ Kp,
    const float* __restrict__ Vp, float* __restrict__ O)
{
    extern __shared__ float sm[];
    float* Qs = sm;             // [64][64]
    float* Ks = sm + 4096;      // [kk][j] stride 65
    float* Vs = Ks + 4160;      // [key][dim] stride 64
    float* Ps = Vs + 4096;      // [i][k] stride 64

    int qt = blockIdx.x, h = blockIdx.y, b = blockIdx.z;
    int t = threadIdx.x, tx = t & 15, ty = t >> 4;
    int i0 = ty * 4, j0 = tx * 4;

    const float* Qg = Q  + (((size_t)(b * H_ + h)) * S_ + qt * 64) * DH_;
    const float* Kg = Kp + ((size_t)(b * H_ + h)) * S_ * DH_;
    const float* Vg = Vp + ((size_t)(b * H_ + h)) * S_ * DH_;

    for (int i = t; i < 1024; i += 256)
        ((float4*)Qs)[i] = ((const float4*)Qg)[i];

    float mrow[4], lrow[4], o[4][4];
    #pragma unroll
    for (int i = 0; i < 4; i++) {
        mrow[i] = neg_inf(); lrow[i] = 0.f;
        #pragma unroll
        for (int j = 0; j < 4; j++) o[i][j] = 0.f;
    }

    for (int kt = 0; kt <= qt; kt++) {
        __syncthreads();
        const float* kg = Kg + (size_t)kt * 64 * DH_;
        for (int idx = t; idx < 4096; idx += 256)
            Ks[(idx & 63) * 65 + (idx >> 6)] = kg[idx];
        const float* vg = Vg + (size_t)kt * 64 * DH_;
        for (int i = t; i < 1024; i += 256)
            ((float4*)Vs)[i] = ((const float4*)vg)[i];
        __syncthreads();

        float s[4][4];
        #pragma unroll
        for (int i = 0; i < 4; i++)
            #pragma unroll
            for (int j = 0; j < 4; j++) s[i][j] = 0.f;

        for (int kk = 0; kk < 64; kk++) {
            float qr[4], kr[4];
            #pragma unroll
            for (int i = 0; i < 4; i++) qr[i] = Qs[(i0 + i) * 64 + kk];
            #pragma unroll
            for (int j = 0; j < 4; j++) kr[j] = Ks[kk * 65 + j0 + j];
            #pragma unroll
            for (int i = 0; i < 4; i++)
                #pragma unroll
                for (int j = 0; j < 4; j++)
                    s[i][j] = fmaf(qr[i], kr[j], s[i][j]);
        }
        #pragma unroll
        for (int i = 0; i < 4; i++)
            #pragma unroll
            for (int j = 0; j < 4; j++) s[i][j] *= 0.125f;  // DH^-0.5

        if (kt == qt) {
            #pragma unroll
            for (int i = 0; i < 4; i++)
                #pragma unroll
                for (int j = 0; j < 4; j++)
                    if (j0 + j > i0 + i) s[i][j] = neg_inf();
        }

        #pragma unroll
        for (int i = 0; i < 4; i++) {
            float mx = fmaxf(fmaxf(s[i][0], s[i][1]), fmaxf(s[i][2], s[i][3]));
            #pragma unroll
            for (int off = 8; off; off >>= 1)
                mx = fmaxf(mx, __shfl_xor_sync(0xffffffffu, mx, off));
            float mn = fmaxf(mrow[i], mx);
            float corr = __expf(mrow[i] - mn);
            mrow[i] = mn;
            float rs = 0.f;
            #pragma unroll
            for (int j = 0; j < 4; j++) {
                float p = __expf(s[i][j] - mn);
                s[i][j] = p; rs += p;
            }
            #pragma unroll
            for (int off = 8; off; off >>= 1)
                rs += __shfl_xor_sync(0xffffffffu, rs, off);
            lrow[i] = lrow[i] * corr + rs;
            #pragma unroll
            for (int j = 0; j < 4; j++) {
                o[i][j] *= corr;
                Ps[(i0 + i) * 64 + j0 + j] = s[i][j];
            }
        }
        __syncthreads();

        for (int kk = 0; kk < 64; kk++) {
            float pr[4];
            #pragma unroll
            for (int i = 0; i < 4; i++) pr[i] = Ps[(i0 + i) * 64 + kk];
            float4 vv = *(const float4*)(&Vs[kk * 64 + j0]);
            #pragma unroll
            for (int i = 0; i < 4; i++) {
                o[i][0] = fmaf(pr[i], vv.x, o[i][0]);
                o[i][1] = fmaf(pr[i], vv.y, o[i][1]);
                o[i][2] = fmaf(pr[i], vv.z, o[i][2]);
                o[i][3] = fmaf(pr[i], vv.w, o[i][3]);
            }
        }
    }

    #pragma unroll
    for (int i = 0; i < 4; i++) {
        float inv = 1.0f / lrow[i];
        int sidx = qt * 64 + i0 + i;
        float4 o4 = make_float4(o[i][0]*inv, o[i][1]*inv, o[i][2]*inv, o[i][3]*inv);
        *(float4*)(O + ((size_t)b * S_ + sidx) * E_ + h * DH_ + j0) = o4;
    }
}

// ---------------- host launcher ----------------
extern "C" void kernel_launch(void* const* d_in, const int* in_sizes, int n_in,
                              void* d_out, int out_size)
{
    const float* x   = (const float*)d_in[0];
    const float* Wq  = (const float*)d_in[1];
    const float* Wk  = (const float*)d_in[2];
    const float* Wv  = (const float*)d_in[3];
    const float* Wo  = (const float*)d_in[4];
    const float* bo  = (const float*)d_in[5];
    const float* W1  = (const float*)d_in[6];
    const float* b1  = (const float*)d_in[7];
    const float* W2  = (const float*)d_in[8];
    const float* b2  = (const float*)d_in[9];
    const float* g1  = (const float*)d_in[10];
    const float* be1 = (const float*)d_in[11];
    const float* g2  = (const float*)d_in[12];
    const float* be2 = (const float*)d_in[13];
    float* out = (float*)d_out;

    float *nx, *q, *k, *v, *attn, *x1, *nx2, *ffn;
    cudaGetSymbolAddress((void**)&nx,   g_nx);
    cudaGetSymbolAddress((void**)&q,    g_q);
    cudaGetSymbolAddress((void**)&k,    g_k);
    cudaGetSymbolAddress((void**)&v,    g_v);
    cudaGetSymbolAddress((void**)&attn, g_attn);
    cudaGetSymbolAddress((void**)&x1,   g_x1);
    cudaGetSymbolAddress((void**)&nx2,  g_nx2);
    cudaGetSymbolAddress((void**)&ffn,  g_ffn);

    const int FLASH_SMEM = (4096 + 4160 + 4096 + 4096) * 4;  // 65792 B
    cudaFuncSetAttribute(flash_kernel, cudaFuncAttributeMaxDynamicSharedMemorySize, FLASH_SMEM);

    // 1. LN1
    ln_kernel<<<TOK, 256>>>(x, g1, be1, nx);
    // 2. Q, K, V projections
    dim3 gq(E_ / 128, TOK / 128);
    gemm_qkv_kernel<<<gq, 256>>>(nx, Wq, q);
    gemm_qkv_kernel<<<gq, 256>>>(nx, Wk, k);
    gemm_qkv_kernel<<<gq, 256>>>(nx, Wv, v);
    // 3. causal flash attention -> concat layout
    dim3 gf(S_ / 64, H_, B_);
    flash_kernel<<<gf, 256, FLASH_SMEM>>>(q, k, v, attn);
    // 4. output projection + residual
    gemm_ep_kernel<false, true><<<dim3(E_ / 128, TOK / 128), 256>>>(
        attn, Wo, bo, x, x1, TOK, E_, E_);
    // 5. LN2
    ln_kernel<<<TOK, 256>>>(x1, g2, be2, nx2);
    // 6. FFN1 (bias + relu)
    gemm_ep_kernel<true, false><<<dim3(FF_ / 128, TOK / 128), 256>>>(
        nx2, W1, b1, nullptr, ffn, TOK, FF_, E_);
    // 7. FFN2 (bias + residual) -> final output
    gemm_ep_kernel<false, true><<<dim3(E_ / 128, TOK / 128), 256>>>(
        ffn, W2, b2, x1, out, TOK, E_, FF_);
}

// round 4
// speedup vs baseline: 1.6224x; 1.6224x over previous
#include <cuda_runtime.h>
#include <cuda_bf16.h>
#include <cstdint>

#define B_   2
#define S_   2048
#define E_   1024
#define H_   16
#define DH_  64
#define FF_  4096
#define TOK  (B_*S_)   // 4096
#define NQKV 3072

// ---------------- scratch (no allocs allowed) ----------------
__device__ __nv_bfloat16 g_nx_hi [TOK*(size_t)E_],  g_nx_lo [TOK*(size_t)E_];
__device__ __nv_bfloat16 g_wqkv_hi[(size_t)NQKV*E_], g_wqkv_lo[(size_t)NQKV*E_];
__device__ __nv_bfloat16 g_wo_hi [(size_t)E_*E_],   g_wo_lo [(size_t)E_*E_];
__device__ __nv_bfloat16 g_w1_hi [(size_t)FF_*E_],  g_w1_lo [(size_t)FF_*E_];
__device__ __nv_bfloat16 g_w2_hi [(size_t)E_*FF_],  g_w2_lo [(size_t)E_*FF_];
__device__ float g_q[(size_t)B_*H_*S_*DH_];
__device__ float g_k[(size_t)B_*H_*S_*DH_];
__device__ float g_v[(size_t)B_*H_*S_*DH_];
__device__ __nv_bfloat16 g_attn_hi[TOK*(size_t)E_], g_attn_lo[TOK*(size_t)E_];
__device__ float g_x1[TOK*(size_t)E_];
__device__ __nv_bfloat16 g_nx2_hi[TOK*(size_t)E_],  g_nx2_lo[TOK*(size_t)E_];
__device__ __nv_bfloat16 g_ffn_hi[TOK*(size_t)FF_], g_ffn_lo[TOK*(size_t)FF_];

__device__ __forceinline__ float neg_inf() { return __int_as_float(0xff800000u); }

// ---------------- PTX helpers (all base-sm_80/90 features, no arch-specific) --
__device__ __forceinline__ uint32_t smem_u32(const void* p) {
    uint32_t a;
    asm("{ .reg .u64 t; cvta.to.shared.u64 t, %1; cvt.u32.u64 %0, t; }" : "=r"(a) : "l"(p));
    return a;
}
__device__ __forceinline__ void cp16(uint32_t s, const void* g) {
    asm volatile("cp.async.cg.shared.global [%0], [%1], 16;" :: "r"(s), "l"(g));
}
#define CP_COMMIT() asm volatile("cp.async.commit_group;" ::: "memory")
#define CP_WAIT(n)  asm volatile("cp.async.wait_group %0;" :: "n"(n) : "memory")

__device__ __forceinline__ void ldm_x4(uint32_t& r0, uint32_t& r1, uint32_t& r2,
                                       uint32_t& r3, uint32_t a) {
    asm volatile("ldmatrix.sync.aligned.m8n8.x4.shared.b16 {%0,%1,%2,%3}, [%4];"
                 : "=r"(r0), "=r"(r1), "=r"(r2), "=r"(r3) : "r"(a));
}
__device__ __forceinline__ void mma16816(float* c, uint32_t a0, uint32_t a1,
                                         uint32_t a2, uint32_t a3,
                                         uint32_t b0, uint32_t b1) {
    asm volatile(
        "mma.sync.aligned.m16n8k16.row.col.f32.bf16.bf16.f32 "
        "{%0,%1,%2,%3},{%4,%5,%6,%7},{%8,%9},{%0,%1,%2,%3};"
        : "+f"(c[0]), "+f"(c[1]), "+f"(c[2]), "+f"(c[3])
        : "r"(a0), "r"(a1), "r"(a2), "r"(a3), "r"(b0), "r"(b1));
}

// ---------------- LayerNorm + bf16 split: one block per token ----------------
__global__ void __launch_bounds__(256) ln_split_kernel(
    const float* __restrict__ x, const float* __restrict__ g,
    const float* __restrict__ bta,
    __nv_bfloat16* __restrict__ ohi, __nv_bfloat16* __restrict__ olo)
{
    __shared__ float sh1[8], sh2[8];
    int tok = blockIdx.x;
    int t = threadIdx.x;
    const float4* xr = (const float4*)(x + (size_t)tok * E_);
    float4 v = xr[t];
    float sum = v.x + v.y + v.z + v.w;
    float sq  = v.x*v.x + v.y*v.y + v.z*v.z + v.w*v.w;
    #pragma unroll
    for (int o = 16; o > 0; o >>= 1) {
        sum += __shfl_xor_sync(0xffffffffu, sum, o);
        sq  += __shfl_xor_sync(0xffffffffu, sq,  o);
    }
    if ((t & 31) == 0) { sh1[t >> 5] = sum; sh2[t >> 5] = sq; }
    __syncthreads();
    if (t < 32) {
        sum = (t < 8) ? sh1[t] : 0.f;
        sq  = (t < 8) ? sh2[t] : 0.f;
        #pragma unroll
        for (int o = 4; o > 0; o >>= 1) {
            sum += __shfl_xor_sync(0xffffffffu, sum, o);
            sq  += __shfl_xor_sync(0xffffffffu, sq,  o);
        }
        if (t == 0) { sh1[0] = sum; sh2[0] = sq; }
    }
    __syncthreads();
    sum = sh1[0]; sq = sh2[0];
    float mu  = sum * (1.0f / E_);
    float var = sq * (1.0f / E_) - mu * mu;
    float rs  = rsqrtf(var + 1e-5f);
    float4 gv = ((const float4*)g)[t];
    float4 bv = ((const float4*)bta)[t];
    float o4[4];
    o4[0] = (v.x - mu) * rs * gv.x + bv.x;
    o4[1] = (v.y - mu) * rs * gv.y + bv.y;
    o4[2] = (v.z - mu) * rs * gv.z + bv.z;
    o4[3] = (v.w - mu) * rs * gv.w + bv.w;
    size_t base = (size_t)tok * E_ + t * 4;
    __nv_bfloat16 h[4], l[4];
    #pragma unroll
    for (int i = 0; i < 4; i++) {
        h[i] = __float2bfloat16(o4[i]);
        l[i] = __float2bfloat16(o4[i] - __bfloat162float(h[i]));
    }
    *(__nv_bfloat162*)(ohi + base)     = __halves2bfloat162(h[0], h[1]);
    *(__nv_bfloat162*)(ohi + base + 2) = __halves2bfloat162(h[2], h[3]);
    *(__nv_bfloat162*)(olo + base)     = __halves2bfloat162(l[0], l[1]);
    *(__nv_bfloat162*)(olo + base + 2) = __halves2bfloat162(l[2], l[3]);
}

// ---------------- weight transpose + split: W[K,N] -> Wt[N,K] hi/lo ----------
__global__ void __launch_bounds__(256) wt_split_kernel(
    const float* __restrict__ W, int K, int N,
    __nv_bfloat16* __restrict__ ohi, __nv_bfloat16* __restrict__ olo)
{
    __shared__ float t[32][33];
    int k0 = blockIdx.x * 32, n0 = blockIdx.y * 32;
    int tx = threadIdx.x & 31, ty = threadIdx.x >> 5;
    #pragma unroll
    for (int r = 0; r < 4; r++)
        t[ty + 8*r][tx] = W[(size_t)(k0 + ty + 8*r) * N + n0 + tx];
    __syncthreads();
    #pragma unroll
    for (int r = 0; r < 4; r++) {
        float v = t[tx][ty + 8*r];
        __nv_bfloat16 h = __float2bfloat16(v);
        __nv_bfloat16 l = __float2bfloat16(v - __bfloat162float(h));
        size_t o = (size_t)(n0 + ty + 8*r) * K + k0 + tx;
        ohi[o] = h; olo[o] = l;
    }
}

// QKV weights [H,E,DH] x3 -> fused Wt[3072, E] hi/lo (row n: mat=n>>10,h,d)
__global__ void __launch_bounds__(256) wqkv_split_kernel(
    const float* __restrict__ Wq, const float* __restrict__ Wk,
    const float* __restrict__ Wv,
    __nv_bfloat16* __restrict__ ohi, __nv_bfloat16* __restrict__ olo)
{
    __shared__ float t[32][33];
    int e0 = blockIdx.x * 32, n0 = blockIdx.y * 32;
    const float* Wm = (n0 < 1024) ? Wq : (n0 < 2048) ? Wk : Wv;
    int nn = n0 & 1023;
    int h = nn >> 6, d0 = nn & 63;
    int tx = threadIdx.x & 31, ty = threadIdx.x >> 5;
    #pragma unroll
    for (int r = 0; r < 4; r++)
        t[ty + 8*r][tx] = Wm[((size_t)h * E_ + e0 + ty + 8*r) * DH_ + d0 + tx];
    __syncthreads();
    #pragma unroll
    for (int r = 0; r < 4; r++) {
        float v = t[tx][ty + 8*r];
        __nv_bfloat16 hh = __float2bfloat16(v);
        __nv_bfloat16 ll = __float2bfloat16(v - __bfloat162float(hh));
        size_t o = (size_t)(n0 + ty + 8*r) * E_ + e0 + tx;
        ohi[o] = hh; olo[o] = ll;
    }
}

// ---------------- HMMA GEMM: C[M,N] = A[M,K]*Bt[N,K]^T, 3-term bf16 split ------
// Virtual K = 3K via slabs: (Ahi,Bhi), (Alo,Bhi), (Ahi,Blo)
// MODE 0: QKV scatter to q/k/v [B,H,S,DH]
// MODE 1/3: + bias + res -> o0 fp32
// MODE 2: relu(+bias) -> oh/ol bf16 split
#define BK     32
#define LDS    40
#define AELEMS (128 * LDS)             // 5120 bf16
#define ABYTES (AELEMS * 2)            // 10240
#define STG_BYTES (2 * ABYTES)         // A + B per stage
#define GEMM_SMEM (4 * STG_BYTES)      // 81920

template<int MODE>
__global__ void __launch_bounds__(256, 1) gemm_mma_kernel(
    const __nv_bfloat16* __restrict__ Ahi, const __nv_bfloat16* __restrict__ Alo,
    const __nv_bfloat16* __restrict__ Bhi, const __nv_bfloat16* __restrict__ Blo,
    const float* __restrict__ bias, const float* __restrict__ res,
    float* __restrict__ o0, float* __restrict__ o1, float* __restrict__ o2,
    __nv_bfloat16* __restrict__ oh, __nv_bfloat16* __restrict__ ol,
    int K, int ldC)
{
    extern __shared__ __nv_bfloat16 smbuf[];
    const uint32_t sbase = smem_u32(smbuf);
    const int NIT = 3 * K / BK;
    const int t = threadIdx.x;
    const int wid = t >> 5, lane = t & 31;
    const int bm = blockIdx.y * 128, bn = blockIdx.x * 128;
    const int wm = (wid & 1) * 64, wn = (wid >> 1) * 32;

    // slab-mapped source pointers for virtual-K chunk i
    auto aptr = [&](int i) -> const __nv_bfloat16* {
        int kc = i * BK;
        const __nv_bfloat16* s = (kc >= K && kc < 2*K) ? Alo : Ahi;
        return s + (size_t)bm * K + (kc & (K - 1));
    };
    auto bptr = [&](int i) -> const __nv_bfloat16* {
        int kc = i * BK;
        const __nv_bfloat16* s = (kc >= 2*K) ? Blo : Bhi;
        return s + (size_t)bn * K + (kc & (K - 1));
    };
    auto load_stage = [&](int st, const __nv_bfloat16* Ap, const __nv_bfloat16* Bp) {
        uint32_t sa = sbase + st * STG_BYTES;
        #pragma unroll
        for (int p = 0; p < 2; p++) {
            int idx = t + p * 256;
            int row = idx >> 2, ch = idx & 3;
            uint32_t off = (uint32_t)(row * LDS + ch * 8) * 2;
            cp16(sa + off,          Ap + (size_t)row * K + ch * 8);
            cp16(sa + ABYTES + off, Bp + (size_t)row * K + ch * 8);
        }
    };

    // prologue: 3 stages in flight
    #pragma unroll
    for (int s = 0; s < 3; s++) { load_stage(s, aptr(s), bptr(s)); CP_COMMIT(); }

    float c[4][4][4];
    #pragma unroll
    for (int mt = 0; mt < 4; mt++)
        #pragma unroll
        for (int nt = 0; nt < 4; nt++)
            #pragma unroll
            for (int e = 0; e < 4; e++) c[mt][nt][e] = 0.f;

    for (int i = 0; i < NIT; i++) {
        CP_WAIT(2);
        __syncthreads();
        if (i + 3 < NIT) load_stage((i + 3) & 3, aptr(i + 3), bptr(i + 3));
        CP_COMMIT();

        uint32_t sa = sbase + (i & 3) * STG_BYTES;
        uint32_t sb = sa + ABYTES;
        #pragma unroll
        for (int ks = 0; ks < 2; ks++) {
            uint32_t a[4][4];
            #pragma unroll
            for (int mt = 0; mt < 4; mt++) {
                uint32_t addr = sa + (uint32_t)(((wm + mt*16 + (lane & 15)) * LDS
                                  + ks*16 + (lane >> 4) * 8) * 2);
                ldm_x4(a[mt][0], a[mt][1], a[mt][2], a[mt][3], addr);
            }
            uint32_t b[4][2];
            #pragma unroll
            for (int np = 0; np < 2; np++) {
                int nrow = wn + np*16 + (lane & 7) + ((lane >> 4) << 3);
                int ncol = ks*16 + (((lane >> 3) & 1) << 3);
                uint32_t addr = sb + (uint32_t)((nrow * LDS + ncol) * 2);
                uint32_t r0, r1, r2, r3;
                ldm_x4(r0, r1, r2, r3, addr);
                b[2*np][0] = r0; b[2*np][1] = r1;
                b[2*np+1][0] = r2; b[2*np+1][1] = r3;
            }
            #pragma unroll
            for (int mt = 0; mt < 4; mt++)
                #pragma unroll
                for (int nt = 0; nt < 4; nt++)
                    mma16816(c[mt][nt], a[mt][0], a[mt][1], a[mt][2], a[mt][3],
                             b[nt][0], b[nt][1]);
        }
    }

    // ---------------- epilogue ----------------
    const int r = lane >> 2, cq = (lane & 3) * 2;
    #pragma unroll
    for (int mt = 0; mt < 4; mt++) {
        #pragma unroll
        for (int half = 0; half < 2; half++) {
            int m = bm + wm + mt * 16 + r + half * 8;
            #pragma unroll
            for (int nt = 0; nt < 4; nt++) {
                int n = bn + wn + nt * 8 + cq;
                float v0 = c[mt][nt][half * 2 + 0];
                float v1 = c[mt][nt][half * 2 + 1];
                if (MODE == 0) {
                    int mat = n >> 10;
                    float* qkv = (mat == 0) ? o0 : (mat == 1) ? o1 : o2;
                    int hh = (n & 1023) >> 6, d = n & 63;
                    int bb = m >> 11, srow = m & (S_ - 1);
                    float* p = qkv + (((size_t)(bb * H_ + hh) * S_ + srow) << 6) + d;
                    *(float2*)p = make_float2(v0, v1);
                } else if (MODE == 2) {
                    float2 bv = *(const float2*)(bias + n);
                    v0 = fmaxf(v0 + bv.x, 0.f);
                    v1 = fmaxf(v1 + bv.y, 0.f);
                    __nv_bfloat16 h0 = __float2bfloat16(v0);
                    __nv_bfloat16 h1 = __float2bfloat16(v1);
                    __nv_bfloat16 l0 = __float2bfloat16(v0 - __bfloat162float(h0));
                    __nv_bfloat16 l1 = __float2bfloat16(v1 - __bfloat162float(h1));
                    size_t base = (size_t)m * ldC + n;
                    *(__nv_bfloat162*)(oh + base) = __halves2bfloat162(h0, h1);
                    *(__nv_bfloat162*)(ol + base) = __halves2bfloat162(l0, l1);
                } else {
                    size_t base = (size_t)m * ldC + n;
                    float2 bv = *(const float2*)(bias + n);
                    float2 rv = *(const float2*)(res + base);
                    *(float2*)(o0 + base) = make_float2(v0 + bv.x + rv.x,
                                                        v1 + bv.y + rv.y);
                }
            }
        }
    }
}

// ---------------- flash attention (causal), 64x64 tiles, bf16-split output ----
__global__ void __launch_bounds__(256) flash_kernel(
    const float* __restrict__ Q, const float* __restrict__ Kp,
    const float* __restrict__ Vp,
    __nv_bfloat16* __restrict__ Ohi, __nv_bfloat16* __restrict__ Olo)
{
    extern __shared__ float sm[];
    float* Qs = sm;             // [64][64]
    float* Ks = sm + 4096;      // [kk][j] stride 65
    float* Vs = Ks + 4160;      // [key][dim] stride 64
    float* Ps = Vs + 4096;      // [i][k] stride 64

    int qt = blockIdx.x, h = blockIdx.y, b = blockIdx.z;
    int t = threadIdx.x, tx = t & 15, ty = t >> 4;
    int i0 = ty * 4, j0 = tx * 4;

    const float* Qg = Q  + (((size_t)(b * H_ + h)) * S_ + qt * 64) * DH_;
    const float* Kg = Kp + ((size_t)(b * H_ + h)) * S_ * DH_;
    const float* Vg = Vp + ((size_t)(b * H_ + h)) * S_ * DH_;

    for (int i = t; i < 1024; i += 256)
        ((float4*)Qs)[i] = ((const float4*)Qg)[i];

    float mrow[4], lrow[4], o[4][4];
    #pragma unroll
    for (int i = 0; i < 4; i++) {
        mrow[i] = neg_inf(); lrow[i] = 0.f;
        #pragma unroll
        for (int j = 0; j < 4; j++) o[i][j] = 0.f;
    }

    for (int kt = 0; kt <= qt; kt++) {
        __syncthreads();
        const float* kg = Kg + (size_t)kt * 64 * DH_;
        for (int idx = t; idx < 4096; idx += 256)
            Ks[(idx & 63) * 65 + (idx >> 6)] = kg[idx];
        const float* vg = Vg + (size_t)kt * 64 * DH_;
        for (int i = t; i < 1024; i += 256)
            ((float4*)Vs)[i] = ((const float4*)vg)[i];
        __syncthreads();

        float s[4][4];
        #pragma unroll
        for (int i = 0; i < 4; i++)
            #pragma unroll
            for (int j = 0; j < 4; j++) s[i][j] = 0.f;

        for (int kk = 0; kk < 64; kk++) {
            float qr[4], kr[4];
            #pragma unroll
            for (int i = 0; i < 4; i++) qr[i] = Qs[(i0 + i) * 64 + kk];
            #pragma unroll
            for (int j = 0; j < 4; j++) kr[j] = Ks[kk * 65 + j0 + j];
            #pragma unroll
            for (int i = 0; i < 4; i++)
                #pragma unroll
                for (int j = 0; j < 4; j++)
                    s[i][j] = fmaf(qr[i], kr[j], s[i][j]);
        }
        #pragma unroll
        for (int i = 0; i < 4; i++)
            #pragma unroll
            for (int j = 0; j < 4; j++) s[i][j] *= 0.125f;

        if (kt == qt) {
            #pragma unroll
            for (int i = 0; i < 4; i++)
                #pragma unroll
                for (int j = 0; j < 4; j++)
                    if (j0 + j > i0 + i) s[i][j] = neg_inf();
        }

        #pragma unroll
        for (int i = 0; i < 4; i++) {
            float mx = fmaxf(fmaxf(s[i][0], s[i][1]), fmaxf(s[i][2], s[i][3]));
            #pragma unroll
            for (int off = 8; off; off >>= 1)
                mx = fmaxf(mx, __shfl_xor_sync(0xffffffffu, mx, off));
            float mn = fmaxf(mrow[i], mx);
            float corr = __expf(mrow[i] - mn);
            mrow[i] = mn;
            float rs = 0.f;
            #pragma unroll
            for (int j = 0; j < 4; j++) {
                float p = __expf(s[i][j] - mn);
                s[i][j] = p; rs += p;
            }
            #pragma unroll
            for (int off = 8; off; off >>= 1)
                rs += __shfl_xor_sync(0xffffffffu, rs, off);
            lrow[i] = lrow[i] * corr + rs;
            #pragma unroll
            for (int j = 0; j < 4; j++) {
                o[i][j] *= corr;
                Ps[(i0 + i) * 64 + j0 + j] = s[i][j];
            }
        }
        __syncthreads();

        for (int kk = 0; kk < 64; kk++) {
            float pr[4];
            #pragma unroll
            for (int i = 0; i < 4; i++) pr[i] = Ps[(i0 + i) * 64 + kk];
            float4 vv = *(const float4*)(&Vs[kk * 64 + j0]);
            #pragma unroll
            for (int i = 0; i < 4; i++) {
                o[i][0] = fmaf(pr[i], vv.x, o[i][0]);
                o[i][1] = fmaf(pr[i], vv.y, o[i][1]);
                o[i][2] = fmaf(pr[i], vv.z, o[i][2]);
                o[i][3] = fmaf(pr[i], vv.w, o[i][3]);
            }
        }
    }

    #pragma unroll
    for (int i = 0; i < 4; i++) {
        float inv = 1.0f / lrow[i];
        int sidx = qt * 64 + i0 + i;
        size_t base = ((size_t)b * S_ + sidx) * E_ + h * DH_ + j0;
        __nv_bfloat16 hh[4], ll[4];
        #pragma unroll
        for (int j = 0; j < 4; j++) {
            float v = o[i][j] * inv;
            hh[j] = __float2bfloat16(v);
            ll[j] = __float2bfloat16(v - __bfloat162float(hh[j]));
        }
        *(__nv_bfloat162*)(Ohi + base)     = __halves2bfloat162(hh[0], hh[1]);
        *(__nv_bfloat162*)(Ohi + base + 2) = __halves2bfloat162(hh[2], hh[3]);
        *(__nv_bfloat162*)(Olo + base)     = __halves2bfloat162(ll[0], ll[1]);
        *(__nv_bfloat162*)(Olo + base + 2) = __halves2bfloat162(ll[2], ll[3]);
    }
}

// ---------------- host launcher ----------------
extern "C" void kernel_launch(void* const* d_in, const int* in_sizes, int n_in,
                              void* d_out, int out_size)
{
    const float* x   = (const float*)d_in[0];
    const float* Wq  = (const float*)d_in[1];
    const float* Wk  = (const float*)d_in[2];
    const float* Wv  = (const float*)d_in[3];
    const float* Wo  = (const float*)d_in[4];
    const float* bo  = (const float*)d_in[5];
    const float* W1  = (const float*)d_in[6];
    const float* b1  = (const float*)d_in[7];
    const float* W2  = (const float*)d_in[8];
    const float* b2  = (const float*)d_in[9];
    const float* g1  = (const float*)d_in[10];
    const float* be1 = (const float*)d_in[11];
    const float* g2  = (const float*)d_in[12];
    const float* be2 = (const float*)d_in[13];
    float* out = (float*)d_out;

    void *nx_hi, *nx_lo, *wqkv_hi, *wqkv_lo, *wo_hi, *wo_lo, *w1_hi, *w1_lo,
         *w2_hi, *w2_lo, *q, *k, *v, *attn_hi, *attn_lo, *x1, *nx2_hi, *nx2_lo,
         *ffn_hi, *ffn_lo;
    cudaGetSymbolAddress(&nx_hi, g_nx_hi);   cudaGetSymbolAddress(&nx_lo, g_nx_lo);
    cudaGetSymbolAddress(&wqkv_hi, g_wqkv_hi); cudaGetSymbolAddress(&wqkv_lo, g_wqkv_lo);
    cudaGetSymbolAddress(&wo_hi, g_wo_hi);   cudaGetSymbolAddress(&wo_lo, g_wo_lo);
    cudaGetSymbolAddress(&w1_hi, g_w1_hi);   cudaGetSymbolAddress(&w1_lo, g_w1_lo);
    cudaGetSymbolAddress(&w2_hi, g_w2_hi);   cudaGetSymbolAddress(&w2_lo, g_w2_lo);
    cudaGetSymbolAddress(&q, g_q); cudaGetSymbolAddress(&k, g_k); cudaGetSymbolAddress(&v, g_v);
    cudaGetSymbolAddress(&attn_hi, g_attn_hi); cudaGetSymbolAddress(&attn_lo, g_attn_lo);
    cudaGetSymbolAddress(&x1, g_x1);
    cudaGetSymbolAddress(&nx2_hi, g_nx2_hi); cudaGetSymbolAddress(&nx2_lo, g_nx2_lo);
    cudaGetSymbolAddress(&ffn_hi, g_ffn_hi); cudaGetSymbolAddress(&ffn_lo, g_ffn_lo);

    cudaFuncSetAttribute(gemm_mma_kernel<0>, cudaFuncAttributeMaxDynamicSharedMemorySize, GEMM_SMEM);
    cudaFuncSetAttribute(gemm_mma_kernel<1>, cudaFuncAttributeMaxDynamicSharedMemorySize, GEMM_SMEM);
    cudaFuncSetAttribute(gemm_mma_kernel<2>, cudaFuncAttributeMaxDynamicSharedMemorySize, GEMM_SMEM);
    cudaFuncSetAttribute(gemm_mma_kernel<3>, cudaFuncAttributeMaxDynamicSharedMemorySize, GEMM_SMEM);
    const int FLASH_SMEM = (4096 + 4160 + 4096 + 4096) * 4;
    cudaFuncSetAttribute(flash_kernel, cudaFuncAttributeMaxDynamicSharedMemorySize, FLASH_SMEM);

    // 1. weight transpose+split
    wqkv_split_kernel<<<dim3(E_/32, NQKV/32), 256>>>(Wq, Wk, Wv,
        (__nv_bfloat16*)wqkv_hi, (__nv_bfloat16*)wqkv_lo);
    wt_split_kernel<<<dim3(E_/32, E_/32), 256>>>(Wo, E_, E_,
        (__nv_bfloat16*)wo_hi, (__nv_bfloat16*)wo_lo);
    wt_split_kernel<<<dim3(E_/32, FF_/32), 256>>>(W1, E_, FF_,
        (__nv_bfloat16*)w1_hi, (__nv_bfloat16*)w1_lo);
    wt_split_kernel<<<dim3(FF_/32, E_/32), 256>>>(W2, FF_, E_,
        (__nv_bfloat16*)w2_hi, (__nv_bfloat16*)w2_lo);
    // 2. LN1 (+split)
    ln_split_kernel<<<TOK, 256>>>(x, g1, be1,
        (__nv_bfloat16*)nx_hi, (__nv_bfloat16*)nx_lo);
    // 3. fused QKV GEMM (N=3072) -> q,k,v
    gemm_mma_kernel<0><<<dim3(NQKV/128, TOK/128), 256, GEMM_SMEM>>>(
        (__nv_bfloat16*)nx_hi, (__nv_bfloat16*)nx_lo,
        (__nv_bfloat16*)wqkv_hi, (__nv_bfloat16*)wqkv_lo,
        nullptr, nullptr, (float*)q, (float*)k, (float*)v, nullptr, nullptr,
        E_, 0);
    // 4. flash attention -> attn hi/lo
    flash_kernel<<<dim3(S_/64, H_, B_), 256, FLASH_SMEM>>>(
        (float*)q, (float*)k, (float*)v,
        (__nv_bfloat16*)attn_hi, (__nv_bfloat16*)attn_lo);
    // 5. output projection + residual -> x1
    gemm_mma_kernel<1><<<dim3(E_/128, TOK/128), 256, GEMM_SMEM>>>(
        (__nv_bfloat16*)attn_hi, (__nv_bfloat16*)attn_lo,
        (__nv_bfloat16*)wo_hi, (__nv_bfloat16*)wo_lo,
        bo, x, (float*)x1, nullptr, nullptr, nullptr, nullptr,
        E_, E_);
    // 6. LN2 (+split)
    ln_split_kernel<<<TOK, 256>>>((float*)x1, g2, be2,
        (__nv_bfloat16*)nx2_hi, (__nv_bfloat16*)nx2_lo);
    // 7. FFN1: relu(+b1) -> ffn hi/lo
    gemm_mma_kernel<2><<<dim3(FF_/128, TOK/128), 256, GEMM_SMEM>>>(
        (__nv_bfloat16*)nx2_hi, (__nv_bfloat16*)nx2_lo,
        (__nv_bfloat16*)w1_hi, (__nv_bfloat16*)w1_lo,
        b1, nullptr, nullptr, nullptr, nullptr,
        (__nv_bfloat16*)ffn_hi, (__nv_bfloat16*)ffn_lo,
        E_, FF_);
    // 8. FFN2: +b2 +x1 -> out
    gemm_mma_kernel<3><<<dim3(E_/128, TOK/128), 256, GEMM_SMEM>>>(
        (__nv_bfloat16*)ffn_hi, (__nv_bfloat16*)ffn_lo,
        (__nv_bfloat16*)w2_hi, (__nv_bfloat16*)w2_lo,
        b2, (float*)x1, out, nullptr, nullptr, nullptr, nullptr,
        FF_, E_);
}